// round 10
// baseline (speedup 1.0000x reference)
#include <cuda_runtime.h>
#include <math.h>

// ---------------- problem constants ----------------
#define NTOK      8192            // B*S = 4*2048
#define D_MODEL   1024
#define N_EXPERTS 8
#define N_FEAT    16
#define RAW_FEAT  512
#define PROJ_DIM  256
#define R_IN      1280
#define R_HID     256
#define E_HID     256

// output layout (floats) : next_hidden | stage_out | gate | scaled_logits | group | rule
#define OFF_STAGE 8388608ull
#define OFF_GATE  16777216ull
#define OFF_SLOG  16842752ull
#define OFF_GRP   16908288ull
#define OFF_RULE  16941056ull

// ---------------- device scratch (no allocations allowed) ----------------
__device__ float g_hnorm[(size_t)NTOK * D_MODEL];
__device__ float g_P1   [(size_t)NTOK * PROJ_DIM];
__device__ float g_P2   [(size_t)NTOK * PROJ_DIM];
__device__ float g_RHs  [(size_t)NTOK * R_HID];
__device__ float g_H1   [(size_t)N_EXPERTS * NTOK * E_HID];
__device__ int   g_tok  [N_EXPERTS * NTOK];
__device__ float g_wt   [N_EXPERTS * NTOK];
__device__ int   g_cnt  [N_EXPERTS];

// ---------------- helpers ----------------
__device__ __forceinline__ float gelu_tanh(float x) {
    float x3 = x * x * x;
    return 0.5f * x * (1.0f + tanhf(0.7978845608028654f * (x + 0.044715f * x3)));
}

// ================= K1: layernorm + init =================
__global__ __launch_bounds__(256) void k_layernorm(
    const float* __restrict__ hidden,
    const float* __restrict__ ln_g,
    const float* __restrict__ ln_b,
    float* __restrict__ out)
{
    int t   = blockIdx.x;
    int tid = threadIdx.x;
    const float* x = hidden + (size_t)t * D_MODEL;

    float v[4], s = 0.f, s2 = 0.f;
#pragma unroll
    for (int j = 0; j < 4; j++) {
        v[j] = x[tid + 256 * j];
        s  += v[j];
        s2 += v[j] * v[j];
    }
#pragma unroll
    for (int o = 16; o; o >>= 1) {
        s  += __shfl_down_sync(0xffffffffu, s,  o);
        s2 += __shfl_down_sync(0xffffffffu, s2, o);
    }
    __shared__ float ps[8], ps2[8];
    __shared__ float mu_s, rs_s;
    int w = tid >> 5, l = tid & 31;
    if (l == 0) { ps[w] = s; ps2[w] = s2; }
    __syncthreads();
    if (tid == 0) {
        float S = 0.f, S2 = 0.f;
#pragma unroll
        for (int i = 0; i < 8; i++) { S += ps[i]; S2 += ps2[i]; }
        float mu  = S * (1.0f / D_MODEL);
        float var = S2 * (1.0f / D_MODEL) - mu * mu;
        mu_s = mu;
        rs_s = rsqrtf(var + 1e-5f);
    }
    __syncthreads();
    float mu = mu_s, rs = rs_s;
#pragma unroll
    for (int j = 0; j < 4; j++) {
        int d = tid + 256 * j;
        float hn = (v[j] - mu) * rs * ln_g[d] + ln_b[d];
        g_hnorm[(size_t)t * D_MODEL + d] = hn;
        out[OFF_STAGE + (size_t)t * D_MODEL + d] = 0.0f;
    }
    if (t == 0 && tid < N_EXPERTS) g_cnt[tid] = 0;
}

// ================= 64x64x8 double-buffered SGEMM, 4x8 microtile, 128 threads =================
// MODE 0: plain C = act(A@B + bias)
// MODE 1: expert GEMM1 (gathered A rows via g_tok), C = gelu(...) compacted
// MODE 2: expert GEMM2, gate-weighted atomicAdd scatter into stage_out
// MODE 3: concat-A (A for k<ksplit, A2 for k>=ksplit)
template<int MODE, int ACT>
__global__ __launch_bounds__(128, 6) void gemm_t(
    const float* __restrict__ A,  int lda,
    const float* __restrict__ A2, int lda2, int ksplit,
    const float* __restrict__ B,  int ldb,
    const float* __restrict__ bias,
    float* __restrict__ C, int ldc, int K, int Mfull)
{
    __shared__ float As[2][8][64];
    __shared__ float Bs[2][8][64];
    __shared__ int   tok_s[64];
    __shared__ float wt_s[64];

    const int t  = threadIdx.x;
    const int m0 = blockIdx.x * 64;
    const int n0 = blockIdx.y * 64;
    const int e  = blockIdx.z;

    int M = Mfull;
    if (MODE == 1 || MODE == 2) {
        M = g_cnt[e];
        if (m0 >= M) return;
        B    += (size_t)e * K * ldb;
        bias += (size_t)e * ldc;
        if (MODE == 1) C += (size_t)e * NTOK * ldc;
        if (MODE == 2) A += (size_t)e * NTOK * lda;
        if (t < 64) {
            int idx = e * NTOK + min(m0 + t, M - 1);
            tok_s[t] = g_tok[idx];
            if (MODE == 2) wt_s[t] = g_wt[idx];
        }
        __syncthreads();
    }

    // per-thread roles
    const int arow = t >> 1, akq = (t & 1) * 4;   // A ldg: row, k-quad (64 rows x 2 quads)
    const int bkr  = t >> 4, bnc = (t & 15) * 4;  // B ldg: one float4 (8 k x 64 n)
    const int ty = t >> 3, tx = t & 7;            // compute: 16x8 thread grid

    size_t rowi;
    if (MODE == 1)      rowi = (size_t)tok_s[arow];
    else if (MODE == 2) rowi = (size_t)min(m0 + arow, M - 1);
    else                rowi = (size_t)(m0 + arow);
    const float* Abase  = A + rowi * lda + akq;
    const float* A2base = (MODE == 3) ? (A2 + rowi * lda2 + akq) : A;
    const float* Bbase  = B + (size_t)bkr * ldb + n0 + bnc;

#define LOAD_A(K0, V0) do {                                                  \
        const float* _p = (MODE == 3 && (K0) >= ksplit)                      \
                        ? (A2base + ((K0) - ksplit)) : (Abase + (K0));       \
        V0 = *reinterpret_cast<const float4*>(_p);                           \
    } while (0)

#define STORE_A(BUF, V0) do {                                                \
        As[BUF][akq + 0][arow] = V0.x; As[BUF][akq + 1][arow] = V0.y;        \
        As[BUF][akq + 2][arow] = V0.z; As[BUF][akq + 3][arow] = V0.w;        \
    } while (0)

    // preload tile 0
    {
        float4 a0;
        LOAD_A(0, a0);
        float4 b0 = *reinterpret_cast<const float4*>(Bbase);
        STORE_A(0, a0);
        *reinterpret_cast<float4*>(&Bs[0][bkr][bnc]) = b0;
    }
    __syncthreads();

    float acc[4][8];
#pragma unroll
    for (int i = 0; i < 4; i++)
#pragma unroll
        for (int j = 0; j < 8; j++) acc[i][j] = 0.f;

    int buf = 0;
    for (int k0 = 8; k0 < K; k0 += 8) {
        float4 na0;
        LOAD_A(k0, na0);
        float4 nb0 = *reinterpret_cast<const float4*>(Bbase + (size_t)k0 * ldb);
#pragma unroll
        for (int kk = 0; kk < 8; kk++) {
            float a[4], b[8];
            *reinterpret_cast<float4*>(&a[0]) = *reinterpret_cast<const float4*>(&As[buf][kk][ty * 4]);
            *reinterpret_cast<float4*>(&b[0]) = *reinterpret_cast<const float4*>(&Bs[buf][kk][tx * 4]);
            *reinterpret_cast<float4*>(&b[4]) = *reinterpret_cast<const float4*>(&Bs[buf][kk][tx * 4 + 32]);
#pragma unroll
            for (int i = 0; i < 4; i++)
#pragma unroll
                for (int j = 0; j < 8; j++)
                    acc[i][j] = fmaf(a[i], b[j], acc[i][j]);
        }
        int nb = buf ^ 1;
        STORE_A(nb, na0);
        *reinterpret_cast<float4*>(&Bs[nb][bkr][bnc]) = nb0;
        __syncthreads();
        buf = nb;
    }
#pragma unroll
    for (int kk = 0; kk < 8; kk++) {
        float a[4], b[8];
        *reinterpret_cast<float4*>(&a[0]) = *reinterpret_cast<const float4*>(&As[buf][kk][ty * 4]);
        *reinterpret_cast<float4*>(&b[0]) = *reinterpret_cast<const float4*>(&Bs[buf][kk][tx * 4]);
        *reinterpret_cast<float4*>(&b[4]) = *reinterpret_cast<const float4*>(&Bs[buf][kk][tx * 4 + 32]);
#pragma unroll
        for (int i = 0; i < 4; i++)
#pragma unroll
            for (int j = 0; j < 8; j++)
                acc[i][j] = fmaf(a[i], b[j], acc[i][j]);
    }

    // epilogue
    float bb[8];
#pragma unroll
    for (int j = 0; j < 4; j++) {
        bb[j]     = bias[n0 + tx * 4 + j];
        bb[4 + j] = bias[n0 + 32 + tx * 4 + j];
    }

#pragma unroll
    for (int i = 0; i < 4; i++) {
        int rl = ty * 4 + i;
        int m  = m0 + rl;
        if (MODE == 0 || MODE == 3) {
            float4 v0, v1;
            float* p0 = &v0.x;
            float* p1 = &v1.x;
#pragma unroll
            for (int j = 0; j < 4; j++) {
                float x0 = acc[i][j]     + bb[j];
                float x1 = acc[i][4 + j] + bb[4 + j];
                if (ACT) { x0 = gelu_tanh(x0); x1 = gelu_tanh(x1); }
                p0[j] = x0; p1[j] = x1;
            }
            *reinterpret_cast<float4*>(&C[(size_t)m * ldc + n0 + tx * 4])      = v0;
            *reinterpret_cast<float4*>(&C[(size_t)m * ldc + n0 + 32 + tx * 4]) = v1;
        } else if (MODE == 1) {
            if (m < M) {
                float4 v0, v1;
                float* p0 = &v0.x;
                float* p1 = &v1.x;
#pragma unroll
                for (int j = 0; j < 4; j++) {
                    p0[j] = gelu_tanh(acc[i][j]     + bb[j]);
                    p1[j] = gelu_tanh(acc[i][4 + j] + bb[4 + j]);
                }
                *reinterpret_cast<float4*>(&C[(size_t)m * ldc + n0 + tx * 4])      = v0;
                *reinterpret_cast<float4*>(&C[(size_t)m * ldc + n0 + 32 + tx * 4]) = v1;
            }
        } else {  // MODE == 2
            if (m < M) {
                int   tok = tok_s[rl];
                float wgt = wt_s[rl];
                float* dst = C + (size_t)tok * ldc + n0;
#pragma unroll
                for (int j = 0; j < 4; j++) {
                    atomicAdd(&dst[tx * 4 + j],      (acc[i][j]     + bb[j])     * wgt);
                    atomicAdd(&dst[32 + tx * 4 + j], (acc[i][4 + j] + bb[4 + j]) * wgt);
                }
            }
        }
    }
#undef LOAD_A
#undef STORE_A
}

// ================= K5: router logits, top-2 softmax, small outputs, dispatch =================
__global__ __launch_bounds__(256) void k_router(
    const float* __restrict__ r_w2, const float* __restrict__ r_b2,
    const float* __restrict__ feat,
    const float* __restrict__ rr_w, const float* __restrict__ rr_b,
    float* __restrict__ out)
{
    int w = threadIdx.x >> 5, l = threadIdx.x & 31;
    int t = blockIdx.x * 8 + w;
    const float* rh = g_RHs + (size_t)t * R_HID;

    float acc[8] = {};
    for (int k = l; k < R_HID; k += 32) {
        float v = rh[k];
#pragma unroll
        for (int e = 0; e < 8; e++) acc[e] = fmaf(v, r_w2[k * 8 + e], acc[e]);
    }
#pragma unroll
    for (int o = 16; o; o >>= 1)
#pragma unroll
        for (int e = 0; e < 8; e++) acc[e] += __shfl_down_sync(0xffffffffu, acc[e], o);

    if (l == 0) {
        float lg[8];
#pragma unroll
        for (int e = 0; e < 8; e++) lg[e] = acc[e] + r_b2[e];
        int i1 = 0; float m1 = lg[0];
#pragma unroll
        for (int e = 1; e < 8; e++) if (lg[e] > m1) { m1 = lg[e]; i1 = e; }
        float m2 = -3.4e38f;
#pragma unroll
        for (int e = 0; e < 8; e++) if (e != i1 && lg[e] > m2) m2 = lg[e];
        float Z = 0.f, g[8];
#pragma unroll
        for (int e = 0; e < 8; e++) {
            if (lg[e] >= m2) { g[e] = expf(lg[e] - m1); Z += g[e]; }
            else g[e] = 0.f;
        }
        float invZ = 1.0f / Z;
#pragma unroll
        for (int e = 0; e < 8; e++) {
            g[e] *= invZ;
            out[OFF_GATE + (size_t)t * 8 + e] = g[e];
            out[OFF_SLOG + (size_t)t * 8 + e] = lg[e];
        }
#pragma unroll
        for (int gi = 0; gi < 4; gi++)
            out[OFF_GRP + (size_t)t * 4 + gi] = g[2 * gi] + g[2 * gi + 1];
        float fv[16];
#pragma unroll
        for (int i = 0; i < 16; i++) fv[i] = feat[(size_t)t * 16 + i];
#pragma unroll
        for (int e = 0; e < 8; e++) {
            float r = rr_b[e];
#pragma unroll
            for (int i = 0; i < 16; i++) r = fmaf(fv[i], rr_w[i * 8 + e], r);
            out[OFF_RULE + (size_t)t * 8 + e] = r;
        }
#pragma unroll
        for (int e = 0; e < 8; e++) {
            if (g[e] > 0.f) {
                int p = atomicAdd(&g_cnt[e], 1);
                g_tok[e * NTOK + p] = t;
                g_wt [e * NTOK + p] = g[e];
            }
        }
    }
}

// ================= K8: next_hidden = hidden + alpha * stage_out =================
__global__ __launch_bounds__(256) void k_finalize(
    const float* __restrict__ hidden,
    const float* __restrict__ alpha,
    float* __restrict__ out)
{
    size_t i = ((size_t)blockIdx.x * 256 + threadIdx.x) * 4;
    float a = alpha[0];
    float4 h = *reinterpret_cast<const float4*>(hidden + i);
    float4 s = *reinterpret_cast<const float4*>(out + OFF_STAGE + i);
    float4 r;
    r.x = h.x + a * s.x;
    r.y = h.y + a * s.y;
    r.z = h.z + a * s.z;
    r.w = h.w + a * s.w;
    *reinterpret_cast<float4*>(out + i) = r;
}

// ================= host launcher =================
extern "C" void kernel_launch(void* const* d_in, const int* in_sizes, int n_in,
                              void* d_out, int out_size)
{
    const float* hidden = (const float*)d_in[0];
    const float* feat   = (const float*)d_in[1];
    const float* bank   = (const float*)d_in[2];
    // d_in[3] = item_seq_len (unused by reference outputs)
    const float* ln_g   = (const float*)d_in[4];
    const float* ln_b   = (const float*)d_in[5];
    const float* fp_w1  = (const float*)d_in[6];
    const float* fp_b1  = (const float*)d_in[7];
    const float* fp_w2  = (const float*)d_in[8];
    const float* fp_b2  = (const float*)d_in[9];
    const float* r_w1   = (const float*)d_in[10];
    const float* r_b1   = (const float*)d_in[11];
    const float* r_w2   = (const float*)d_in[12];
    const float* r_b2   = (const float*)d_in[13];
    const float* rr_w   = (const float*)d_in[14];
    const float* rr_b   = (const float*)d_in[15];
    const float* e_w1   = (const float*)d_in[16];
    const float* e_b1   = (const float*)d_in[17];
    const float* e_w2   = (const float*)d_in[18];
    const float* e_b2   = (const float*)d_in[19];
    const float* alpha  = (const float*)d_in[20];
    float* out = (float*)d_out;

    float *p_P1, *p_P2, *p_RHs, *p_hn, *p_H1;
    cudaGetSymbolAddress((void**)&p_P1,  g_P1);
    cudaGetSymbolAddress((void**)&p_P2,  g_P2);
    cudaGetSymbolAddress((void**)&p_RHs, g_RHs);
    cudaGetSymbolAddress((void**)&p_hn,  g_hnorm);
    cudaGetSymbolAddress((void**)&p_H1,  g_H1);

    // K1: layernorm -> g_hnorm, zero stage_out, reset counters
    k_layernorm<<<NTOK, 256>>>(hidden, ln_g, ln_b, out);

    // K2: P1 = gelu(bank @ fp_w1 + fp_b1)   [8192x512 @ 512x256], 512 CTAs
    gemm_t<0, 1><<<dim3(NTOK / 64, PROJ_DIM / 64), 128>>>(
        bank, RAW_FEAT, nullptr, 0, 0, fp_w1, PROJ_DIM, fp_b1,
        p_P1, PROJ_DIM, RAW_FEAT, NTOK);

    // K3: P2 = P1 @ fp_w2 + fp_b2           [8192x256 @ 256x256], 512 CTAs
    gemm_t<0, 0><<<dim3(NTOK / 64, PROJ_DIM / 64), 128>>>(
        p_P1, PROJ_DIM, nullptr, 0, 0, fp_w2, PROJ_DIM, fp_b2,
        p_P2, PROJ_DIM, PROJ_DIM, NTOK);

    // K4: RH = gelu(concat(hnorm,P2) @ r_w1 + r_b1)  [8192x1280 @ 1280x256], 512 CTAs
    gemm_t<3, 1><<<dim3(NTOK / 64, R_HID / 64), 128>>>(
        p_hn, D_MODEL, p_P2, PROJ_DIM, D_MODEL, r_w1, R_HID, r_b1,
        p_RHs, R_HID, R_IN, NTOK);

    // K5: logits, top-2 softmax, small outputs, expert dispatch
    k_router<<<NTOK / 8, 256>>>(r_w2, r_b2, feat, rr_w, rr_b, out);

    // K6: per-expert gathered GEMM1 (gelu) -> g_H1, ~1024 active CTAs
    gemm_t<1, 1><<<dim3(NTOK / 64, E_HID / 64, N_EXPERTS), 128>>>(
        p_hn, D_MODEL, nullptr, 0, 0, e_w1, E_HID, e_b1,
        p_H1, E_HID, D_MODEL, 0);

    // K7: per-expert GEMM2, gate-weighted atomic accumulate, ~4096 active CTAs
    gemm_t<2, 0><<<dim3(NTOK / 64, D_MODEL / 64, N_EXPERTS), 128>>>(
        p_H1, E_HID, nullptr, 0, 0, e_w2, D_MODEL, e_b2,
        out + OFF_STAGE, D_MODEL, E_HID, 0);

    // K8: next_hidden = hidden + alpha * stage_out
    k_finalize<<<(NTOK * D_MODEL) / (256 * 4), 256>>>(hidden, alpha, out);
}

// round 12
// speedup vs baseline: 1.1192x; 1.1192x over previous
#include <cuda_runtime.h>
#include <math.h>
#include <stdint.h>

// ---------------- problem constants ----------------
#define NTOK      8192            // B*S = 4*2048
#define D_MODEL   1024
#define N_EXPERTS 8
#define N_FEAT    16
#define RAW_FEAT  512
#define PROJ_DIM  256
#define R_IN      1280
#define R_HID     256
#define E_HID     256

// output layout (floats) : next_hidden | stage_out | gate | scaled_logits | group | rule
#define OFF_STAGE 8388608ull
#define OFF_GATE  16777216ull
#define OFF_SLOG  16842752ull
#define OFF_GRP   16908288ull
#define OFF_RULE  16941056ull

// ---------------- device scratch (no allocations allowed) ----------------
__device__ float g_hnorm[(size_t)NTOK * D_MODEL];
__device__ float g_RI   [(size_t)NTOK * R_IN];
__device__ float g_P1   [(size_t)NTOK * PROJ_DIM];
__device__ float g_RHs  [(size_t)NTOK * R_HID];
__device__ float g_H1   [(size_t)N_EXPERTS * NTOK * E_HID];
__device__ int   g_tok  [N_EXPERTS * NTOK];
__device__ float g_wt   [N_EXPERTS * NTOK];
__device__ int   g_cnt  [N_EXPERTS];

// ---------------- helpers ----------------
__device__ __forceinline__ float gelu_tanh(float x) {
    float x3 = x * x * x;
    return 0.5f * x * (1.0f + tanhf(0.7978845608028654f * (x + 0.044715f * x3)));
}
__device__ __forceinline__ uint32_t f2tf32(float x) {
    uint32_t r;
    asm("cvt.rna.tf32.f32 %0, %1;" : "=r"(r) : "f"(x));
    return r;
}
__device__ __forceinline__ void mma_tf32(float* c, const uint32_t* a, const uint32_t* b) {
    asm volatile(
        "mma.sync.aligned.m16n8k8.row.col.f32.tf32.tf32.f32 "
        "{%0,%1,%2,%3}, {%4,%5,%6,%7}, {%8,%9}, {%0,%1,%2,%3};"
        : "+f"(c[0]), "+f"(c[1]), "+f"(c[2]), "+f"(c[3])
        : "r"(a[0]), "r"(a[1]), "r"(a[2]), "r"(a[3]), "r"(b[0]), "r"(b[1]));
}

// ================= K1: layernorm + init =================
__global__ __launch_bounds__(256) void k_layernorm(
    const float* __restrict__ hidden,
    const float* __restrict__ ln_g,
    const float* __restrict__ ln_b,
    float* __restrict__ out)
{
    int t   = blockIdx.x;
    int tid = threadIdx.x;
    const float* x = hidden + (size_t)t * D_MODEL;

    float v[4], s = 0.f, s2 = 0.f;
#pragma unroll
    for (int j = 0; j < 4; j++) {
        v[j] = x[tid + 256 * j];
        s  += v[j];
        s2 += v[j] * v[j];
    }
#pragma unroll
    for (int o = 16; o; o >>= 1) {
        s  += __shfl_down_sync(0xffffffffu, s,  o);
        s2 += __shfl_down_sync(0xffffffffu, s2, o);
    }
    __shared__ float ps[8], ps2[8];
    __shared__ float mu_s, rs_s;
    int w = tid >> 5, l = tid & 31;
    if (l == 0) { ps[w] = s; ps2[w] = s2; }
    __syncthreads();
    if (tid == 0) {
        float S = 0.f, S2 = 0.f;
#pragma unroll
        for (int i = 0; i < 8; i++) { S += ps[i]; S2 += ps2[i]; }
        float mu  = S * (1.0f / D_MODEL);
        float var = S2 * (1.0f / D_MODEL) - mu * mu;
        mu_s = mu;
        rs_s = rsqrtf(var + 1e-5f);
    }
    __syncthreads();
    float mu = mu_s, rs = rs_s;
#pragma unroll
    for (int j = 0; j < 4; j++) {
        int d = tid + 256 * j;
        float hn = (v[j] - mu) * rs * ln_g[d] + ln_b[d];
        g_hnorm[(size_t)t * D_MODEL + d] = hn;
        g_RI[(size_t)t * R_IN + d]       = hn;
        out[OFF_STAGE + (size_t)t * D_MODEL + d] = 0.0f;
    }
    if (t == 0 && tid < N_EXPERTS) g_cnt[tid] = 0;
}

// ================= 128x128x8 double-buffered SGEMM (router path, fp32-exact, R7 geometry) ==========
template<int ACT>
__global__ __launch_bounds__(256, 2) void gemm128(
    const float* __restrict__ A, int lda,
    const float* __restrict__ B, int ldb,
    const float* __restrict__ bias,
    float* __restrict__ C, int ldc, int K)
{
    __shared__ float As[2][8][128];
    __shared__ float Bs[2][8][128];

    const int t  = threadIdx.x;
    const int m0 = blockIdx.x * 128;
    const int n0 = blockIdx.y * 128;

    const int arow = t >> 1, akq = (t & 1) * 4;
    const int bkr  = t >> 5, bnc = (t & 31) * 4;
    const int ty = t >> 4, tx = t & 15;

    const float* Aptr = A + (size_t)(m0 + arow) * lda + akq;
    const float* Bptr = B + (size_t)bkr * ldb + n0 + bnc;

    {
        float4 av = *reinterpret_cast<const float4*>(Aptr);
        float4 bv = *reinterpret_cast<const float4*>(Bptr);
        As[0][akq + 0][arow] = av.x;
        As[0][akq + 1][arow] = av.y;
        As[0][akq + 2][arow] = av.z;
        As[0][akq + 3][arow] = av.w;
        *reinterpret_cast<float4*>(&Bs[0][bkr][bnc]) = bv;
    }
    __syncthreads();

    float acc[8][8];
#pragma unroll
    for (int i = 0; i < 8; i++)
#pragma unroll
        for (int j = 0; j < 8; j++) acc[i][j] = 0.f;

    int buf = 0;
    for (int k0 = 8; k0 < K; k0 += 8) {
        float4 av2 = *reinterpret_cast<const float4*>(Aptr + k0);
        float4 bv2 = *reinterpret_cast<const float4*>(Bptr + (size_t)k0 * ldb);
#pragma unroll
        for (int kk = 0; kk < 8; kk++) {
            float a[8], b[8];
            *reinterpret_cast<float4*>(&a[0]) = *reinterpret_cast<const float4*>(&As[buf][kk][ty * 4]);
            *reinterpret_cast<float4*>(&a[4]) = *reinterpret_cast<const float4*>(&As[buf][kk][ty * 4 + 64]);
            *reinterpret_cast<float4*>(&b[0]) = *reinterpret_cast<const float4*>(&Bs[buf][kk][tx * 4]);
            *reinterpret_cast<float4*>(&b[4]) = *reinterpret_cast<const float4*>(&Bs[buf][kk][tx * 4 + 64]);
#pragma unroll
            for (int i = 0; i < 8; i++)
#pragma unroll
                for (int j = 0; j < 8; j++)
                    acc[i][j] = fmaf(a[i], b[j], acc[i][j]);
        }
        int nb = buf ^ 1;
        As[nb][akq + 0][arow] = av2.x;
        As[nb][akq + 1][arow] = av2.y;
        As[nb][akq + 2][arow] = av2.z;
        As[nb][akq + 3][arow] = av2.w;
        *reinterpret_cast<float4*>(&Bs[nb][bkr][bnc]) = bv2;
        __syncthreads();
        buf = nb;
    }
#pragma unroll
    for (int kk = 0; kk < 8; kk++) {
        float a[8], b[8];
        *reinterpret_cast<float4*>(&a[0]) = *reinterpret_cast<const float4*>(&As[buf][kk][ty * 4]);
        *reinterpret_cast<float4*>(&a[4]) = *reinterpret_cast<const float4*>(&As[buf][kk][ty * 4 + 64]);
        *reinterpret_cast<float4*>(&b[0]) = *reinterpret_cast<const float4*>(&Bs[buf][kk][tx * 4]);
        *reinterpret_cast<float4*>(&b[4]) = *reinterpret_cast<const float4*>(&Bs[buf][kk][tx * 4 + 64]);
#pragma unroll
        for (int i = 0; i < 8; i++)
#pragma unroll
            for (int j = 0; j < 8; j++)
                acc[i][j] = fmaf(a[i], b[j], acc[i][j]);
    }

    float bb[8];
#pragma unroll
    for (int j = 0; j < 4; j++) {
        bb[j]     = bias[n0 + tx * 4 + j];
        bb[4 + j] = bias[n0 + 64 + tx * 4 + j];
    }
#pragma unroll
    for (int ih = 0; ih < 2; ih++) {
#pragma unroll
        for (int i = 0; i < 4; i++) {
            int m  = m0 + ih * 64 + ty * 4 + i;
            int ri = ih * 4 + i;
            float4 v0, v1;
            float* p0 = &v0.x;
            float* p1 = &v1.x;
#pragma unroll
            for (int j = 0; j < 4; j++) {
                float x0 = acc[ri][j]     + bb[j];
                float x1 = acc[ri][4 + j] + bb[4 + j];
                if (ACT) { x0 = gelu_tanh(x0); x1 = gelu_tanh(x1); }
                p0[j] = x0; p1[j] = x1;
            }
            *reinterpret_cast<float4*>(&C[(size_t)m * ldc + n0 + tx * 4])      = v0;
            *reinterpret_cast<float4*>(&C[(size_t)m * ldc + n0 + 64 + tx * 4]) = v1;
        }
    }
}

// ================= K5: router logits, top-2 softmax, small outputs, dispatch =================
__global__ __launch_bounds__(256) void k_router(
    const float* __restrict__ r_w2, const float* __restrict__ r_b2,
    const float* __restrict__ feat,
    const float* __restrict__ rr_w, const float* __restrict__ rr_b,
    float* __restrict__ out)
{
    int w = threadIdx.x >> 5, l = threadIdx.x & 31;
    int t = blockIdx.x * 8 + w;
    const float* rh = g_RHs + (size_t)t * R_HID;

    float acc[8] = {};
    for (int k = l; k < R_HID; k += 32) {
        float v = rh[k];
#pragma unroll
        for (int e = 0; e < 8; e++) acc[e] = fmaf(v, r_w2[k * 8 + e], acc[e]);
    }
#pragma unroll
    for (int o = 16; o; o >>= 1)
#pragma unroll
        for (int e = 0; e < 8; e++) acc[e] += __shfl_down_sync(0xffffffffu, acc[e], o);

    if (l == 0) {
        float lg[8];
#pragma unroll
        for (int e = 0; e < 8; e++) lg[e] = acc[e] + r_b2[e];
        int i1 = 0; float m1 = lg[0];
#pragma unroll
        for (int e = 1; e < 8; e++) if (lg[e] > m1) { m1 = lg[e]; i1 = e; }
        float m2 = -3.4e38f;
#pragma unroll
        for (int e = 0; e < 8; e++) if (e != i1 && lg[e] > m2) m2 = lg[e];
        float Z = 0.f, g[8];
#pragma unroll
        for (int e = 0; e < 8; e++) {
            if (lg[e] >= m2) { g[e] = expf(lg[e] - m1); Z += g[e]; }
            else g[e] = 0.f;
        }
        float invZ = 1.0f / Z;
#pragma unroll
        for (int e = 0; e < 8; e++) {
            g[e] *= invZ;
            out[OFF_GATE + (size_t)t * 8 + e] = g[e];
            out[OFF_SLOG + (size_t)t * 8 + e] = lg[e];
        }
#pragma unroll
        for (int gi = 0; gi < 4; gi++)
            out[OFF_GRP + (size_t)t * 4 + gi] = g[2 * gi] + g[2 * gi + 1];
        float fv[16];
#pragma unroll
        for (int i = 0; i < 16; i++) fv[i] = feat[(size_t)t * 16 + i];
#pragma unroll
        for (int e = 0; e < 8; e++) {
            float r = rr_b[e];
#pragma unroll
            for (int i = 0; i < 16; i++) r = fmaf(fv[i], rr_w[i * 8 + e], r);
            out[OFF_RULE + (size_t)t * 8 + e] = r;
        }
#pragma unroll
        for (int e = 0; e < 8; e++) {
            if (g[e] > 0.f) {
                int p = atomicAdd(&g_cnt[e], 1);
                g_tok[e * NTOK + p] = t;
                g_wt [e * NTOK + p] = g[e];
            }
        }
    }
}

// ================= expert GEMMs via mma.sync TF32 =================
// CTA: 256 thr (8 warps), tile M=128 x N=64, K-chunk 32, double-buffered.
// Warp tile 32x32 = 2(M) x 4(N) frags of m16n8k8.
// Fragment-linear smem: A frag = 128 u32 (lane*4+slot), B frag = 64 u32 (lane*2+slot).
// MODE 1: H1 = gelu(hnorm[gathered] @ e_w1 + b1)   (K=1024, B=[e][1024][256])
// MODE 2: stage_out[tok] += wt * (H1 @ e_w2 + b2)  (K=256,  B=[e][256][1024])
// smem u32 layout: A0 @0 (4096), A1 @4096, B0 @8192 (2048), B1 @10240, tok @12288, wt @12416
#define EXP_SMEM_BYTES (12544 * 4)

template<int MODE>
__global__ __launch_bounds__(256, 2) void k_expert_mma(
    const float* __restrict__ Asrc, const float* __restrict__ Bsrc,
    const float* __restrict__ bias, float* __restrict__ C,
    int K, int Ntot)
{
    extern __shared__ uint32_t sm[];
    uint32_t* smA = sm;            // 2 x 4096
    uint32_t* smB = sm + 8192;     // 2 x 2048
    int*      tok_s = (int*)(sm + 12288);
    float*    wt_s  = (float*)(sm + 12416);

    const int t   = threadIdx.x;
    const int e   = blockIdx.z;
    const int m0  = blockIdx.x * 128;
    const int n0  = blockIdx.y * 64;
    const int M   = g_cnt[e];
    if (m0 >= M) return;

    const float* Ae = (MODE == 1) ? Asrc : Asrc + (size_t)e * NTOK * K;
    const float* Be = Bsrc + (size_t)e * K * Ntot + n0;
    const float* be = bias + e * Ntot + n0;

    if (t < 128) {
        int idx = e * NTOK + min(m0 + t, M - 1);
        tok_s[t] = g_tok[idx];
        if (MODE == 2) wt_s[t] = g_wt[idx];
    }
    __syncthreads();

    // ---- staging roles ----
    // A: 128 rows x 32 k / 256 thr: row = t>>1, k-span = (t&1)*16, 4 float4
    const int arow_l = t >> 1;
    const int aks    = (t & 1) * 16;
    const int ami    = arow_l >> 4;
    const int ar     = arow_l & 15;
    const int albase = (ar & 7) * 4;          // lane base (j adds 0..3)
    const int aslotr = (ar >> 3);             // slot row bit
    size_t arow_g;
    if (MODE == 1) arow_g = (size_t)tok_s[arow_l] * (size_t)K;
    else           arow_g = (size_t)min(m0 + arow_l, M - 1) * (size_t)K;
    const float* Ab = Ae + arow_g + aks;

    // B: 32 k x 64 n / 256 thr: krow = t>>3, n-span = (t&7)*8, 2 float4
    const int bkrow = t >> 3;
    const int bns   = (t & 7) * 8;
    const int bki   = bkrow >> 3;
    const int bc    = bkrow & 7;
    const int bslot = bc >> 2;
    const int blc2  = (bc & 3) * 2;
    const int bni   = t & 7;                  // local n-block (bns>>3)
    const float* Bb = Be + (size_t)bkrow * Ntot + bns;

    // ---- compute roles ----
    const int lane = t & 31;
    const int wid  = t >> 5;
    const int wm   = wid >> 1;                // 0..3 -> M rows wm*32
    const int wn   = wid & 1;                 // 0..1 -> N cols wn*32

    float acc[2][4][4];
#pragma unroll
    for (int i = 0; i < 2; i++)
#pragma unroll
        for (int j = 0; j < 4; j++)
#pragma unroll
            for (int q = 0; q < 4; q++) acc[i][j][q] = 0.f;

    float4 av[4], bv[2];

#define LOAD_GMEM(C0) do {                                                       \
        size_t kof = (size_t)(C0) * 32;                                          \
        av[0] = *reinterpret_cast<const float4*>(Ab + kof);                      \
        av[1] = *reinterpret_cast<const float4*>(Ab + kof + 4);                  \
        av[2] = *reinterpret_cast<const float4*>(Ab + kof + 8);                  \
        av[3] = *reinterpret_cast<const float4*>(Ab + kof + 12);                 \
        bv[0] = *reinterpret_cast<const float4*>(Bb + kof * Ntot);               \
        bv[1] = *reinterpret_cast<const float4*>(Bb + kof * Ntot + 4);           \
    } while (0)

#define STAGE(BF) do {                                                           \
        uint32_t* A = smA + (BF) * 4096;                                         \
        uint32_t* B = smB + (BF) * 2048;                                         \
        _Pragma("unroll")                                                        \
        for (int q = 0; q < 4; q++) {                                            \
            int kl  = aks + 4 * q;                                               \
            int fb  = (ami * 4 + (kl >> 3)) * 128 + albase * 4                   \
                    + aslotr + (((kl >> 2) & 1) << 1);                           \
            const float* pv = &av[q].x;                                          \
            _Pragma("unroll")                                                    \
            for (int j = 0; j < 4; j++) A[fb + 4 * j] = f2tf32(pv[j]);           \
        }                                                                        \
        _Pragma("unroll")                                                        \
        for (int h = 0; h < 2; h++) {                                            \
            int fb = (bki * 8 + bni) * 64 + (h * 4) * 8 + blc2 + bslot;          \
            const float* pv = &bv[h].x;                                          \
            _Pragma("unroll")                                                    \
            for (int j = 0; j < 4; j++) B[fb + 8 * j] = f2tf32(pv[j]);           \
        }                                                                        \
    } while (0)

#define COMPUTE(BF) do {                                                         \
        const uint32_t* A = smA + (BF) * 4096;                                   \
        const uint32_t* B = smB + (BF) * 2048;                                   \
        _Pragma("unroll")                                                        \
        for (int ki = 0; ki < 4; ki++) {                                         \
            uint32_t afr[2][4], bfr[4][2];                                       \
            _Pragma("unroll")                                                    \
            for (int ml = 0; ml < 2; ml++)                                       \
                *reinterpret_cast<uint4*>(afr[ml]) =                             \
                    *reinterpret_cast<const uint4*>(                             \
                        A + ((wm * 2 + ml) * 4 + ki) * 128 + lane * 4);          \
            _Pragma("unroll")                                                    \
            for (int nl = 0; nl < 4; nl++)                                       \
                *reinterpret_cast<uint2*>(bfr[nl]) =                             \
                    *reinterpret_cast<const uint2*>(                             \
                        B + (ki * 8 + wn * 4 + nl) * 64 + lane * 2);             \
            _Pragma("unroll")                                                    \
            for (int ml = 0; ml < 2; ml++)                                       \
                _Pragma("unroll")                                                \
                for (int nl = 0; nl < 4; nl++)                                   \
                    mma_tf32(acc[ml][nl], afr[ml], bfr[nl]);                     \
        }                                                                        \
    } while (0)

    const int NC = K / 32;
    LOAD_GMEM(0);
    STAGE(0);
    __syncthreads();
    int buf = 0;
    for (int c = 1; c < NC; c++) {
        LOAD_GMEM(c);
        COMPUTE(buf);
        STAGE(buf ^ 1);
        __syncthreads();
        buf ^= 1;
    }
    COMPUTE(buf);

    // ---- epilogue ----
    const int gr = lane >> 2;             // 0..7
    const int gc = (lane & 3) * 2;        // 0,2,4,6
#pragma unroll
    for (int ml = 0; ml < 2; ml++) {
        int r0 = wm * 32 + ml * 16 + gr;  // local rows r0, r0+8
#pragma unroll
        for (int nl = 0; nl < 4; nl++) {
            int col = wn * 32 + nl * 8 + gc;
            float b0 = be[col], b1 = be[col + 1];
#pragma unroll
            for (int h = 0; h < 2; h++) {
                int rl = r0 + h * 8;
                int m  = m0 + rl;
                if (m < M) {
                    float x0 = acc[ml][nl][h * 2 + 0] + b0;
                    float x1 = acc[ml][nl][h * 2 + 1] + b1;
                    if (MODE == 1) {
                        float2 v = make_float2(gelu_tanh(x0), gelu_tanh(x1));
                        *reinterpret_cast<float2*>(
                            C + ((size_t)e * NTOK + m) * Ntot + n0 + col) = v;
                    } else {
                        int   tok = tok_s[rl];
                        float wgt = wt_s[rl];
                        float* dst = C + (size_t)tok * D_MODEL + n0 + col;
                        atomicAdd(&dst[0], x0 * wgt);
                        atomicAdd(&dst[1], x1 * wgt);
                    }
                }
            }
        }
    }
#undef LOAD_GMEM
#undef STAGE
#undef COMPUTE
}

// ================= K8: next_hidden = hidden + alpha * stage_out =================
__global__ __launch_bounds__(256) void k_finalize(
    const float* __restrict__ hidden,
    const float* __restrict__ alpha,
    float* __restrict__ out)
{
    size_t i = ((size_t)blockIdx.x * 256 + threadIdx.x) * 4;
    float a = alpha[0];
    float4 h = *reinterpret_cast<const float4*>(hidden + i);
    float4 s = *reinterpret_cast<const float4*>(out + OFF_STAGE + i);
    float4 r;
    r.x = h.x + a * s.x;
    r.y = h.y + a * s.y;
    r.z = h.z + a * s.z;
    r.w = h.w + a * s.w;
    *reinterpret_cast<float4*>(out + i) = r;
}

// ================= host launcher =================
extern "C" void kernel_launch(void* const* d_in, const int* in_sizes, int n_in,
                              void* d_out, int out_size)
{
    const float* hidden = (const float*)d_in[0];
    const float* feat   = (const float*)d_in[1];
    const float* bank   = (const float*)d_in[2];
    // d_in[3] = item_seq_len (unused by reference outputs)
    const float* ln_g   = (const float*)d_in[4];
    const float* ln_b   = (const float*)d_in[5];
    const float* fp_w1  = (const float*)d_in[6];
    const float* fp_b1  = (const float*)d_in[7];
    const float* fp_w2  = (const float*)d_in[8];
    const float* fp_b2  = (const float*)d_in[9];
    const float* r_w1   = (const float*)d_in[10];
    const float* r_b1   = (const float*)d_in[11];
    const float* r_w2   = (const float*)d_in[12];
    const float* r_b2   = (const float*)d_in[13];
    const float* rr_w   = (const float*)d_in[14];
    const float* rr_b   = (const float*)d_in[15];
    const float* e_w1   = (const float*)d_in[16];
    const float* e_b1   = (const float*)d_in[17];
    const float* e_w2   = (const float*)d_in[18];
    const float* e_b2   = (const float*)d_in[19];
    const float* alpha  = (const float*)d_in[20];
    float* out = (float*)d_out;

    float *p_RI, *p_P1, *p_RHs, *p_hn, *p_H1;
    cudaGetSymbolAddress((void**)&p_RI,  g_RI);
    cudaGetSymbolAddress((void**)&p_P1,  g_P1);
    cudaGetSymbolAddress((void**)&p_RHs, g_RHs);
    cudaGetSymbolAddress((void**)&p_hn,  g_hnorm);
    cudaGetSymbolAddress((void**)&p_H1,  g_H1);

    cudaFuncSetAttribute(k_expert_mma<1>, cudaFuncAttributeMaxDynamicSharedMemorySize, EXP_SMEM_BYTES);
    cudaFuncSetAttribute(k_expert_mma<2>, cudaFuncAttributeMaxDynamicSharedMemorySize, EXP_SMEM_BYTES);

    // K1: layernorm -> g_hnorm / g_RI[:, :1024], zero stage_out, reset counters
    k_layernorm<<<NTOK, 256>>>(hidden, ln_g, ln_b, out);

    // K2: P1 = gelu(bank @ fp_w1 + fp_b1)   [8192x512 @ 512x256]
    gemm128<1><<<dim3(NTOK / 128, PROJ_DIM / 128), 256>>>(
        bank, RAW_FEAT, fp_w1, PROJ_DIM, fp_b1, p_P1, PROJ_DIM, RAW_FEAT);

    // K3: proj = P1 @ fp_w2 + fp_b2  -> g_RI[:, 1024:1280]
    gemm128<0><<<dim3(NTOK / 128, PROJ_DIM / 128), 256>>>(
        p_P1, PROJ_DIM, fp_w2, PROJ_DIM, fp_b2, p_RI + D_MODEL, R_IN, PROJ_DIM);

    // K4: RH = gelu(RI @ r_w1 + r_b1)        [8192x1280 @ 1280x256]
    gemm128<1><<<dim3(NTOK / 128, R_HID / 128), 256>>>(
        p_RI, R_IN, r_w1, R_HID, r_b1, p_RHs, R_HID, R_IN);

    // K5: logits, top-2 softmax, small outputs, expert dispatch
    k_router<<<NTOK / 8, 256>>>(r_w2, r_b2, feat, rr_w, rr_b, out);

    // K6: per-expert gathered GEMM1 (mma.sync tf32, gelu) -> g_H1
    k_expert_mma<1><<<dim3(NTOK / 128, E_HID / 64, N_EXPERTS), 256, EXP_SMEM_BYTES>>>(
        p_hn, e_w1, e_b1, p_H1, D_MODEL, E_HID);

    // K7: per-expert GEMM2 (mma.sync tf32), gate-weighted atomic accumulate
    k_expert_mma<2><<<dim3(NTOK / 128, D_MODEL / 64, N_EXPERTS), 256, EXP_SMEM_BYTES>>>(
        p_H1, e_w2, e_b2, out + OFF_STAGE, E_HID, D_MODEL);

    // K8: next_hidden = hidden + alpha * stage_out
    k_finalize<<<(NTOK * D_MODEL) / (256 * 4), 256>>>(hidden, alpha, out);
}

// round 13
// speedup vs baseline: 1.2155x; 1.0860x over previous
#include <cuda_runtime.h>
#include <math.h>
#include <stdint.h>

// ---------------- problem constants ----------------
#define NTOK      8192            // B*S = 4*2048
#define D_MODEL   1024
#define N_EXPERTS 8
#define N_FEAT    16
#define RAW_FEAT  512
#define PROJ_DIM  256
#define R_IN      1280
#define R_HID     256
#define E_HID     256

// output layout (floats) : next_hidden | stage_out | gate | scaled_logits | group | rule
#define OFF_STAGE 8388608ull
#define OFF_GATE  16777216ull
#define OFF_SLOG  16842752ull
#define OFF_GRP   16908288ull
#define OFF_RULE  16941056ull

// ---------------- device scratch (no allocations allowed) ----------------
__device__ float g_hnorm[(size_t)NTOK * D_MODEL];
__device__ float g_P1   [(size_t)NTOK * PROJ_DIM];
__device__ float g_XA1  [(size_t)NTOK * R_HID];
__device__ float g_XA2  [(size_t)NTOK * R_HID];
__device__ float g_RHs  [(size_t)NTOK * R_HID];
__device__ float g_Wc   [PROJ_DIM * R_HID];
__device__ float g_cc   [R_HID];
__device__ float g_H1   [(size_t)N_EXPERTS * NTOK * E_HID];
__device__ int   g_tok  [N_EXPERTS * NTOK];
__device__ float g_wt   [N_EXPERTS * NTOK];
__device__ int   g_cnt  [N_EXPERTS];

// ---------------- helpers ----------------
__device__ __forceinline__ float gelu_tanh(float x) {
    float x3 = x * x * x;
    return 0.5f * x * (1.0f + tanhf(0.7978845608028654f * (x + 0.044715f * x3)));
}
__device__ __forceinline__ uint32_t f2tf32(float x) {
    uint32_t r;
    asm("cvt.rna.tf32.f32 %0, %1;" : "=r"(r) : "f"(x));
    return r;
}
__device__ __forceinline__ void mma_tf32(float* c, const uint32_t* a, const uint32_t* b) {
    asm volatile(
        "mma.sync.aligned.m16n8k8.row.col.f32.tf32.tf32.f32 "
        "{%0,%1,%2,%3}, {%4,%5,%6,%7}, {%8,%9}, {%0,%1,%2,%3};"
        : "+f"(c[0]), "+f"(c[1]), "+f"(c[2]), "+f"(c[3])
        : "r"(a[0]), "r"(a[1]), "r"(a[2]), "r"(a[3]), "r"(b[0]), "r"(b[1]));
}

// ================= K1: layernorm + init =================
__global__ __launch_bounds__(256) void k_layernorm(
    const float* __restrict__ hidden,
    const float* __restrict__ ln_g,
    const float* __restrict__ ln_b,
    float* __restrict__ out)
{
    int t   = blockIdx.x;
    int tid = threadIdx.x;
    const float* x = hidden + (size_t)t * D_MODEL;

    float v[4], s = 0.f, s2 = 0.f;
#pragma unroll
    for (int j = 0; j < 4; j++) {
        v[j] = x[tid + 256 * j];
        s  += v[j];
        s2 += v[j] * v[j];
    }
#pragma unroll
    for (int o = 16; o; o >>= 1) {
        s  += __shfl_down_sync(0xffffffffu, s,  o);
        s2 += __shfl_down_sync(0xffffffffu, s2, o);
    }
    __shared__ float ps[8], ps2[8];
    __shared__ float mu_s, rs_s;
    int w = tid >> 5, l = tid & 31;
    if (l == 0) { ps[w] = s; ps2[w] = s2; }
    __syncthreads();
    if (tid == 0) {
        float S = 0.f, S2 = 0.f;
#pragma unroll
        for (int i = 0; i < 8; i++) { S += ps[i]; S2 += ps2[i]; }
        float mu  = S * (1.0f / D_MODEL);
        float var = S2 * (1.0f / D_MODEL) - mu * mu;
        mu_s = mu;
        rs_s = rsqrtf(var + 1e-5f);
    }
    __syncthreads();
    float mu = mu_s, rs = rs_s;
#pragma unroll
    for (int j = 0; j < 4; j++) {
        int d = tid + 256 * j;
        float hn = (v[j] - mu) * rs * ln_g[d] + ln_b[d];
        g_hnorm[(size_t)t * D_MODEL + d] = hn;
        out[OFF_STAGE + (size_t)t * D_MODEL + d] = 0.0f;
    }
    if (t == 0 && tid < N_EXPERTS) g_cnt[tid] = 0;
}

// ================= 128x128x8 double-buffered SGEMM core (fp32-exact) =================
// C = act(A@B + bias + add1 + add2); bias/add1/add2 nullable; act runtime.
__device__ __forceinline__ void gemm_core(
    const float* __restrict__ A, int lda,
    const float* __restrict__ B, int ldb,
    const float* __restrict__ bias,
    const float* __restrict__ add1,
    const float* __restrict__ add2,
    float* __restrict__ C, int ldc,
    int K, int act, int m0, int n0,
    float As[2][8][128], float Bs[2][8][128])
{
    const int t = threadIdx.x;
    const int arow = t >> 1, akq = (t & 1) * 4;
    const int bkr  = t >> 5, bnc = (t & 31) * 4;
    const int ty = t >> 4, tx = t & 15;

    const float* Aptr = A + (size_t)(m0 + arow) * lda + akq;
    const float* Bptr = B + (size_t)bkr * ldb + n0 + bnc;

    {
        float4 av = *reinterpret_cast<const float4*>(Aptr);
        float4 bv = *reinterpret_cast<const float4*>(Bptr);
        As[0][akq + 0][arow] = av.x;
        As[0][akq + 1][arow] = av.y;
        As[0][akq + 2][arow] = av.z;
        As[0][akq + 3][arow] = av.w;
        *reinterpret_cast<float4*>(&Bs[0][bkr][bnc]) = bv;
    }
    __syncthreads();

    float acc[8][8];
#pragma unroll
    for (int i = 0; i < 8; i++)
#pragma unroll
        for (int j = 0; j < 8; j++) acc[i][j] = 0.f;

    int buf = 0;
    for (int k0 = 8; k0 < K; k0 += 8) {
        float4 av2 = *reinterpret_cast<const float4*>(Aptr + k0);
        float4 bv2 = *reinterpret_cast<const float4*>(Bptr + (size_t)k0 * ldb);
#pragma unroll
        for (int kk = 0; kk < 8; kk++) {
            float a[8], b[8];
            *reinterpret_cast<float4*>(&a[0]) = *reinterpret_cast<const float4*>(&As[buf][kk][ty * 4]);
            *reinterpret_cast<float4*>(&a[4]) = *reinterpret_cast<const float4*>(&As[buf][kk][ty * 4 + 64]);
            *reinterpret_cast<float4*>(&b[0]) = *reinterpret_cast<const float4*>(&Bs[buf][kk][tx * 4]);
            *reinterpret_cast<float4*>(&b[4]) = *reinterpret_cast<const float4*>(&Bs[buf][kk][tx * 4 + 64]);
#pragma unroll
            for (int i = 0; i < 8; i++)
#pragma unroll
                for (int j = 0; j < 8; j++)
                    acc[i][j] = fmaf(a[i], b[j], acc[i][j]);
        }
        int nb = buf ^ 1;
        As[nb][akq + 0][arow] = av2.x;
        As[nb][akq + 1][arow] = av2.y;
        As[nb][akq + 2][arow] = av2.z;
        As[nb][akq + 3][arow] = av2.w;
        *reinterpret_cast<float4*>(&Bs[nb][bkr][bnc]) = bv2;
        __syncthreads();
        buf = nb;
    }
#pragma unroll
    for (int kk = 0; kk < 8; kk++) {
        float a[8], b[8];
        *reinterpret_cast<float4*>(&a[0]) = *reinterpret_cast<const float4*>(&As[buf][kk][ty * 4]);
        *reinterpret_cast<float4*>(&a[4]) = *reinterpret_cast<const float4*>(&As[buf][kk][ty * 4 + 64]);
        *reinterpret_cast<float4*>(&b[0]) = *reinterpret_cast<const float4*>(&Bs[buf][kk][tx * 4]);
        *reinterpret_cast<float4*>(&b[4]) = *reinterpret_cast<const float4*>(&Bs[buf][kk][tx * 4 + 64]);
#pragma unroll
        for (int i = 0; i < 8; i++)
#pragma unroll
            for (int j = 0; j < 8; j++)
                acc[i][j] = fmaf(a[i], b[j], acc[i][j]);
    }

    float bb[8];
#pragma unroll
    for (int j = 0; j < 4; j++) {
        bb[j]     = bias ? bias[n0 + tx * 4 + j]      : 0.f;
        bb[4 + j] = bias ? bias[n0 + 64 + tx * 4 + j] : 0.f;
    }
#pragma unroll
    for (int ih = 0; ih < 2; ih++) {
#pragma unroll
        for (int i = 0; i < 4; i++) {
            int m  = m0 + ih * 64 + ty * 4 + i;
            int ri = ih * 4 + i;
            float x[8];
#pragma unroll
            for (int j = 0; j < 4; j++) {
                x[j]     = acc[ri][j]     + bb[j];
                x[4 + j] = acc[ri][4 + j] + bb[4 + j];
            }
            if (add1) {
                float4 u0 = *reinterpret_cast<const float4*>(add1 + (size_t)m * ldc + n0 + tx * 4);
                float4 u1 = *reinterpret_cast<const float4*>(add1 + (size_t)m * ldc + n0 + 64 + tx * 4);
                x[0] += u0.x; x[1] += u0.y; x[2] += u0.z; x[3] += u0.w;
                x[4] += u1.x; x[5] += u1.y; x[6] += u1.z; x[7] += u1.w;
            }
            if (add2) {
                float4 u0 = *reinterpret_cast<const float4*>(add2 + (size_t)m * ldc + n0 + tx * 4);
                float4 u1 = *reinterpret_cast<const float4*>(add2 + (size_t)m * ldc + n0 + 64 + tx * 4);
                x[0] += u0.x; x[1] += u0.y; x[2] += u0.z; x[3] += u0.w;
                x[4] += u1.x; x[5] += u1.y; x[6] += u1.z; x[7] += u1.w;
            }
            if (act) {
#pragma unroll
                for (int j = 0; j < 8; j++) x[j] = gelu_tanh(x[j]);
            }
            float4 v0, v1;
            v0.x = x[0]; v0.y = x[1]; v0.z = x[2]; v0.w = x[3];
            v1.x = x[4]; v1.y = x[5]; v1.z = x[6]; v1.w = x[7];
            *reinterpret_cast<float4*>(&C[(size_t)m * ldc + n0 + tx * 4])      = v0;
            *reinterpret_cast<float4*>(&C[(size_t)m * ldc + n0 + 64 + tx * 4]) = v1;
        }
    }
}

// ================= K2fused: multiplex 4 independent GEMMs in one launch =================
// z=0: P1  = gelu(bank @ fp_w1 + fp_b1)                 [8192x512x256]
// z=1: XA1 = hnorm[:, :512]  @ r_w1[0:512]    + r_b1    [8192x512x256]
// z=2: XA2 = hnorm[:, 512:]  @ r_w1[512:1024]           [8192x512x256]
// z=3: Wc  = fp_w2 @ r_w1[1024:1280] (4 CTAs); cc = fp_b2 @ r_w1[1024:] (1 CTA)
__global__ __launch_bounds__(256, 2) void k_fused(
    const float* __restrict__ bank,
    const float* __restrict__ fp_w1, const float* __restrict__ fp_b1,
    const float* __restrict__ fp_w2, const float* __restrict__ fp_b2,
    const float* __restrict__ r_w1,  const float* __restrict__ r_b1)
{
    __shared__ float As[2][8][128];
    __shared__ float Bs[2][8][128];
    const int z  = blockIdx.z;
    const int bx = blockIdx.x, by = blockIdx.y;
    int m0 = bx * 128, n0 = by * 128;

    const float* A; int lda; const float* B; int ldb;
    const float* bias; float* C; int K; int act;

    if (z == 0) {
        A = bank;  lda = RAW_FEAT; B = fp_w1; ldb = PROJ_DIM;
        bias = fp_b1; C = g_P1; K = RAW_FEAT; act = 1;
    } else if (z == 1) {
        A = g_hnorm; lda = D_MODEL; B = r_w1; ldb = R_HID;
        bias = r_b1; C = g_XA1; K = 512; act = 0;
    } else if (z == 2) {
        A = g_hnorm + 512; lda = D_MODEL; B = r_w1 + 512 * R_HID; ldb = R_HID;
        bias = nullptr; C = g_XA2; K = 512; act = 0;
    } else {
        if (bx == 2 && by == 0) {
            // cc[j] = sum_k fp_b2[k] * r_w1[(1024+k)*256 + j]
            int j = threadIdx.x;
            float s = 0.f;
            for (int k = 0; k < PROJ_DIM; k++)
                s = fmaf(fp_b2[k], r_w1[(size_t)(1024 + k) * R_HID + j], s);
            g_cc[j] = s;
            return;
        }
        if (bx >= 2 || by >= 2) return;
        A = fp_w2; lda = PROJ_DIM; B = r_w1 + 1024 * R_HID; ldb = R_HID;
        bias = nullptr; C = g_Wc; K = PROJ_DIM; act = 0;
    }
    gemm_core(A, lda, B, ldb, bias, nullptr, nullptr, C, R_HID, K, act, m0, n0, As, Bs);
}

// ================= K4b: RH = gelu(P1 @ Wc + XA1 + XA2 + cc) =================
__global__ __launch_bounds__(256, 2) void k_4b()
{
    __shared__ float As[2][8][128];
    __shared__ float Bs[2][8][128];
    gemm_core(g_P1, PROJ_DIM, g_Wc, R_HID, g_cc, g_XA1, g_XA2,
              g_RHs, R_HID, PROJ_DIM, 1, blockIdx.x * 128, blockIdx.y * 128, As, Bs);
}

// ================= K5: router logits, top-2 softmax, small outputs, dispatch =================
__global__ __launch_bounds__(256) void k_router(
    const float* __restrict__ r_w2, const float* __restrict__ r_b2,
    const float* __restrict__ feat,
    const float* __restrict__ rr_w, const float* __restrict__ rr_b,
    float* __restrict__ out)
{
    int w = threadIdx.x >> 5, l = threadIdx.x & 31;
    int t = blockIdx.x * 8 + w;
    const float* rh = g_RHs + (size_t)t * R_HID;

    float acc[8] = {};
    for (int k = l; k < R_HID; k += 32) {
        float v = rh[k];
#pragma unroll
        for (int e = 0; e < 8; e++) acc[e] = fmaf(v, r_w2[k * 8 + e], acc[e]);
    }
#pragma unroll
    for (int o = 16; o; o >>= 1)
#pragma unroll
        for (int e = 0; e < 8; e++) acc[e] += __shfl_down_sync(0xffffffffu, acc[e], o);

    if (l == 0) {
        float lg[8];
#pragma unroll
        for (int e = 0; e < 8; e++) lg[e] = acc[e] + r_b2[e];
        int i1 = 0; float m1 = lg[0];
#pragma unroll
        for (int e = 1; e < 8; e++) if (lg[e] > m1) { m1 = lg[e]; i1 = e; }
        float m2 = -3.4e38f;
#pragma unroll
        for (int e = 0; e < 8; e++) if (e != i1 && lg[e] > m2) m2 = lg[e];
        float Z = 0.f, g[8];
#pragma unroll
        for (int e = 0; e < 8; e++) {
            if (lg[e] >= m2) { g[e] = expf(lg[e] - m1); Z += g[e]; }
            else g[e] = 0.f;
        }
        float invZ = 1.0f / Z;
#pragma unroll
        for (int e = 0; e < 8; e++) {
            g[e] *= invZ;
            out[OFF_GATE + (size_t)t * 8 + e] = g[e];
            out[OFF_SLOG + (size_t)t * 8 + e] = lg[e];
        }
#pragma unroll
        for (int gi = 0; gi < 4; gi++)
            out[OFF_GRP + (size_t)t * 4 + gi] = g[2 * gi] + g[2 * gi + 1];
        float fv[16];
#pragma unroll
        for (int i = 0; i < 16; i++) fv[i] = feat[(size_t)t * 16 + i];
#pragma unroll
        for (int e = 0; e < 8; e++) {
            float r = rr_b[e];
#pragma unroll
            for (int i = 0; i < 16; i++) r = fmaf(fv[i], rr_w[i * 8 + e], r);
            out[OFF_RULE + (size_t)t * 8 + e] = r;
        }
#pragma unroll
        for (int e = 0; e < 8; e++) {
            if (g[e] > 0.f) {
                int p = atomicAdd(&g_cnt[e], 1);
                g_tok[e * NTOK + p] = t;
                g_wt [e * NTOK + p] = g[e];
            }
        }
    }
}

// ================= expert GEMMs via mma.sync TF32 (proven in R11) =================
#define EXP_SMEM_BYTES (12544 * 4)

template<int MODE>
__global__ __launch_bounds__(256, 2) void k_expert_mma(
    const float* __restrict__ Asrc, const float* __restrict__ Bsrc,
    const float* __restrict__ bias, float* __restrict__ C,
    int K, int Ntot)
{
    extern __shared__ uint32_t sm[];
    uint32_t* smA = sm;            // 2 x 4096
    uint32_t* smB = sm + 8192;     // 2 x 2048
    int*      tok_s = (int*)(sm + 12288);
    float*    wt_s  = (float*)(sm + 12416);

    const int t   = threadIdx.x;
    const int e   = blockIdx.z;
    const int m0  = blockIdx.x * 128;
    const int n0  = blockIdx.y * 64;
    const int M   = g_cnt[e];
    if (m0 >= M) return;

    const float* Ae = (MODE == 1) ? Asrc : Asrc + (size_t)e * NTOK * K;
    const float* Be = Bsrc + (size_t)e * K * Ntot + n0;
    const float* be = bias + e * Ntot + n0;

    if (t < 128) {
        int idx = e * NTOK + min(m0 + t, M - 1);
        tok_s[t] = g_tok[idx];
        if (MODE == 2) wt_s[t] = g_wt[idx];
    }
    __syncthreads();

    const int arow_l = t >> 1;
    const int aks    = (t & 1) * 16;
    const int ami    = arow_l >> 4;
    const int ar     = arow_l & 15;
    const int albase = (ar & 7) * 4;
    const int aslotr = (ar >> 3);
    size_t arow_g;
    if (MODE == 1) arow_g = (size_t)tok_s[arow_l] * (size_t)K;
    else           arow_g = (size_t)min(m0 + arow_l, M - 1) * (size_t)K;
    const float* Ab = Ae + arow_g + aks;

    const int bkrow = t >> 3;
    const int bns   = (t & 7) * 8;
    const int bki   = bkrow >> 3;
    const int bc    = bkrow & 7;
    const int bslot = bc >> 2;
    const int blc2  = (bc & 3) * 2;
    const int bni   = t & 7;
    const float* Bb = Be + (size_t)bkrow * Ntot + bns;

    const int lane = t & 31;
    const int wid  = t >> 5;
    const int wm   = wid >> 1;
    const int wn   = wid & 1;

    float acc[2][4][4];
#pragma unroll
    for (int i = 0; i < 2; i++)
#pragma unroll
        for (int j = 0; j < 4; j++)
#pragma unroll
            for (int q = 0; q < 4; q++) acc[i][j][q] = 0.f;

    float4 av[4], bv[2];

#define LOAD_GMEM(C0) do {                                                       \
        size_t kof = (size_t)(C0) * 32;                                          \
        av[0] = *reinterpret_cast<const float4*>(Ab + kof);                      \
        av[1] = *reinterpret_cast<const float4*>(Ab + kof + 4);                  \
        av[2] = *reinterpret_cast<const float4*>(Ab + kof + 8);                  \
        av[3] = *reinterpret_cast<const float4*>(Ab + kof + 12);                 \
        bv[0] = *reinterpret_cast<const float4*>(Bb + kof * Ntot);               \
        bv[1] = *reinterpret_cast<const float4*>(Bb + kof * Ntot + 4);           \
    } while (0)

#define STAGE(BF) do {                                                           \
        uint32_t* A = smA + (BF) * 4096;                                         \
        uint32_t* B = smB + (BF) * 2048;                                         \
        _Pragma("unroll")                                                        \
        for (int q = 0; q < 4; q++) {                                            \
            int kl  = aks + 4 * q;                                               \
            int fb  = (ami * 4 + (kl >> 3)) * 128 + albase * 4                   \
                    + aslotr + (((kl >> 2) & 1) << 1);                           \
            const float* pv = &av[q].x;                                          \
            _Pragma("unroll")                                                    \
            for (int j = 0; j < 4; j++) A[fb + 4 * j] = f2tf32(pv[j]);           \
        }                                                                        \
        _Pragma("unroll")                                                        \
        for (int h = 0; h < 2; h++) {                                            \
            int fb = (bki * 8 + bni) * 64 + (h * 4) * 8 + blc2 + bslot;          \
            const float* pv = &bv[h].x;                                          \
            _Pragma("unroll")                                                    \
            for (int j = 0; j < 4; j++) B[fb + 8 * j] = f2tf32(pv[j]);           \
        }                                                                        \
    } while (0)

#define COMPUTE(BF) do {                                                         \
        const uint32_t* A = smA + (BF) * 4096;                                   \
        const uint32_t* B = smB + (BF) * 2048;                                   \
        _Pragma("unroll")                                                        \
        for (int ki = 0; ki < 4; ki++) {                                         \
            uint32_t afr[2][4], bfr[4][2];                                       \
            _Pragma("unroll")                                                    \
            for (int ml = 0; ml < 2; ml++)                                       \
                *reinterpret_cast<uint4*>(afr[ml]) =                             \
                    *reinterpret_cast<const uint4*>(                             \
                        A + ((wm * 2 + ml) * 4 + ki) * 128 + lane * 4);          \
            _Pragma("unroll")                                                    \
            for (int nl = 0; nl < 4; nl++)                                       \
                *reinterpret_cast<uint2*>(bfr[nl]) =                             \
                    *reinterpret_cast<const uint2*>(                             \
                        B + (ki * 8 + wn * 4 + nl) * 64 + lane * 2);             \
            _Pragma("unroll")                                                    \
            for (int ml = 0; ml < 2; ml++)                                       \
                _Pragma("unroll")                                                \
                for (int nl = 0; nl < 4; nl++)                                   \
                    mma_tf32(acc[ml][nl], afr[ml], bfr[nl]);                     \
        }                                                                        \
    } while (0)

    const int NC = K / 32;
    LOAD_GMEM(0);
    STAGE(0);
    __syncthreads();
    int buf = 0;
    for (int c = 1; c < NC; c++) {
        LOAD_GMEM(c);
        COMPUTE(buf);
        STAGE(buf ^ 1);
        __syncthreads();
        buf ^= 1;
    }
    COMPUTE(buf);

    const int gr = lane >> 2;
    const int gc = (lane & 3) * 2;
#pragma unroll
    for (int ml = 0; ml < 2; ml++) {
        int r0 = wm * 32 + ml * 16 + gr;
#pragma unroll
        for (int nl = 0; nl < 4; nl++) {
            int col = wn * 32 + nl * 8 + gc;
            float b0 = be[col], b1 = be[col + 1];
#pragma unroll
            for (int h = 0; h < 2; h++) {
                int rl = r0 + h * 8;
                int m  = m0 + rl;
                if (m < M) {
                    float x0 = acc[ml][nl][h * 2 + 0] + b0;
                    float x1 = acc[ml][nl][h * 2 + 1] + b1;
                    if (MODE == 1) {
                        float2 v = make_float2(gelu_tanh(x0), gelu_tanh(x1));
                        *reinterpret_cast<float2*>(
                            C + ((size_t)e * NTOK + m) * Ntot + n0 + col) = v;
                    } else {
                        int   tok = tok_s[rl];
                        float wgt = wt_s[rl];
                        float* dst = C + (size_t)tok * D_MODEL + n0 + col;
                        atomicAdd(&dst[0], x0 * wgt);
                        atomicAdd(&dst[1], x1 * wgt);
                    }
                }
            }
        }
    }
#undef LOAD_GMEM
#undef STAGE
#undef COMPUTE
}

// ================= K8: next_hidden = hidden + alpha * stage_out =================
__global__ __launch_bounds__(256) void k_finalize(
    const float* __restrict__ hidden,
    const float* __restrict__ alpha,
    float* __restrict__ out)
{
    size_t i = ((size_t)blockIdx.x * 256 + threadIdx.x) * 4;
    float a = alpha[0];
    float4 h = *reinterpret_cast<const float4*>(hidden + i);
    float4 s = *reinterpret_cast<const float4*>(out + OFF_STAGE + i);
    float4 r;
    r.x = h.x + a * s.x;
    r.y = h.y + a * s.y;
    r.z = h.z + a * s.z;
    r.w = h.w + a * s.w;
    *reinterpret_cast<float4*>(out + i) = r;
}

// ================= host launcher =================
extern "C" void kernel_launch(void* const* d_in, const int* in_sizes, int n_in,
                              void* d_out, int out_size)
{
    const float* hidden = (const float*)d_in[0];
    const float* feat   = (const float*)d_in[1];
    const float* bank   = (const float*)d_in[2];
    // d_in[3] = item_seq_len (unused by reference outputs)
    const float* ln_g   = (const float*)d_in[4];
    const float* ln_b   = (const float*)d_in[5];
    const float* fp_w1  = (const float*)d_in[6];
    const float* fp_b1  = (const float*)d_in[7];
    const float* fp_w2  = (const float*)d_in[8];
    const float* fp_b2  = (const float*)d_in[9];
    const float* r_w1   = (const float*)d_in[10];
    const float* r_b1   = (const float*)d_in[11];
    const float* r_w2   = (const float*)d_in[12];
    const float* r_b2   = (const float*)d_in[13];
    const float* rr_w   = (const float*)d_in[14];
    const float* rr_b   = (const float*)d_in[15];
    const float* e_w1   = (const float*)d_in[16];
    const float* e_b1   = (const float*)d_in[17];
    const float* e_w2   = (const float*)d_in[18];
    const float* e_b2   = (const float*)d_in[19];
    const float* alpha  = (const float*)d_in[20];
    float* out = (float*)d_out;

    float *p_hn, *p_H1;
    cudaGetSymbolAddress((void**)&p_hn, g_hnorm);
    cudaGetSymbolAddress((void**)&p_H1, g_H1);

    cudaFuncSetAttribute(k_expert_mma<1>, cudaFuncAttributeMaxDynamicSharedMemorySize, EXP_SMEM_BYTES);
    cudaFuncSetAttribute(k_expert_mma<2>, cudaFuncAttributeMaxDynamicSharedMemorySize, EXP_SMEM_BYTES);

    // K1: layernorm -> g_hnorm, zero stage_out, reset counters
    k_layernorm<<<NTOK, 256>>>(hidden, ln_g, ln_b, out);

    // K2fused: P1 | XA1 | XA2 | (Wc, cc) — 389 active CTAs, chip-filling
    k_fused<<<dim3(NTOK / 128, 2, 4), 256>>>(
        bank, fp_w1, fp_b1, fp_w2, fp_b2, r_w1, r_b1);

    // K4b: RH = gelu(P1 @ Wc + XA1 + XA2 + cc)
    k_4b<<<dim3(NTOK / 128, 2), 256>>>();

    // K5: logits, top-2 softmax, small outputs, expert dispatch
    k_router<<<NTOK / 8, 256>>>(r_w2, r_b2, feat, rr_w, rr_b, out);

    // K6: per-expert gathered GEMM1 (mma.sync tf32, gelu) -> g_H1
    k_expert_mma<1><<<dim3(NTOK / 128, E_HID / 64, N_EXPERTS), 256, EXP_SMEM_BYTES>>>(
        p_hn, e_w1, e_b1, p_H1, D_MODEL, E_HID);

    // K7: per-expert GEMM2 (mma.sync tf32), gate-weighted atomic accumulate
    k_expert_mma<2><<<dim3(NTOK / 128, D_MODEL / 64, N_EXPERTS), 256, EXP_SMEM_BYTES>>>(
        p_H1, e_w2, e_b2, out + OFF_STAGE, E_HID, D_MODEL);

    // K8: next_hidden = hidden + alpha * stage_out
    k_finalize<<<(NTOK * D_MODEL) / (256 * 4), 256>>>(hidden, alpha, out);
}